// round 16
// baseline (speedup 1.0000x reference)
#include <cuda_runtime.h>
#include <mma.h>
#include <math.h>

using namespace nvcuda;
typedef long long ll;

#define D_    768
#define BSZ   64
#define T_    32
#define NTOK  901
#define NLOC  900
#define DK_   384
#define M_Q   (BSZ * T_)   // 2048
#define GRU_BLOCKS 96

// ---------------- scratch (static device globals; no allocation) ----------------
__device__ float g_t1[BSZ * D_];
__device__ float g_u[BSZ * D_];
__device__ float g_t2[BSZ * D_];
__device__ float g_wx[BSZ * 3 * D_];
__device__ float g_h[BSZ * D_];
__device__ float g_h2[BSZ * D_];
__device__ float g_qemb[M_Q * D_];
__device__ float g_Q[M_Q * D_];
__device__ float g_Qt[2 * M_Q * D_];
__device__ float g_qb[2 * M_Q];
__device__ float g_S[(ll)BSZ * 2 * T_ * NLOC];
__device__ float g_wk[BSZ * 2 * NLOC];
__device__ float g_pctxi[BSZ * 2 * D_];
__device__ float g_pooled[BSZ * D_];
__device__ float g_hcat[BSZ * 2 * D_];
__device__ float g_x1[BSZ * 1024];
__device__ float g_x2[BSZ * 512];
__device__ float g_scal[2];
__device__ int   g_cnt2[2];   // gru per-half barrier counters
__device__ int   g_cntf;      // front kernel barrier counter

// ---------------- device helpers ----------------
__device__ __forceinline__ void gridbar(int* cnt, int target)
{
    __syncthreads();
    if (threadIdx.x == 0) {
        __threadfence();
        atomicAdd(cnt, 1);
        while (*((volatile int*)cnt) < target) {}
        __threadfence();
    }
    __syncthreads();
}

// one 64xK @ KxN -> 64x16 tile; all 256 threads of the block participate.
__device__ void skinny_tile(const float* __restrict__ A, const float* __restrict__ B,
                            const float* __restrict__ bias, float asc, float bsc,
                            float* __restrict__ C, int K, int lda, int ldb, int ldc,
                            int rb, ll bStride, int colBase, bool transb,
                            float (*As)[68], float (*Bs)[17])
{
    const int tid = threadIdx.x;
    const int c = tid & 15, r4 = tid >> 4;
    float acc[4] = {0.f, 0.f, 0.f, 0.f};
    const int am = tid >> 3, ak4 = (tid & 7) * 4;

    float4 pa0, pa1, pb;
    {
        const float* ap0 = (rb > 0) ? A + (ll)am * bStride : A + (ll)am * lda;
        const float* ap1 = (rb > 0) ? A + (ll)(32 + am) * bStride : A + (ll)(32 + am) * lda;
        pa0 = *(const float4*)(ap0 + ak4);
        pa1 = *(const float4*)(ap1 + ak4);
        if (tid < 128) {
            if (transb)
                pb = *(const float4*)(B + (ll)(colBase + (tid >> 3)) * ldb + (tid & 7) * 4);
            else
                pb = *(const float4*)(B + (ll)(tid >> 2) * ldb + colBase + (tid & 3) * 4);
        }
    }

    for (int kt = 0; kt < K; kt += 32) {
        As[ak4 + 0][am] = pa0.x; As[ak4 + 1][am] = pa0.y;
        As[ak4 + 2][am] = pa0.z; As[ak4 + 3][am] = pa0.w;
        As[ak4 + 0][32 + am] = pa1.x; As[ak4 + 1][32 + am] = pa1.y;
        As[ak4 + 2][32 + am] = pa1.z; As[ak4 + 3][32 + am] = pa1.w;
        if (tid < 128) {
            if (transb) {
                int n = tid >> 3, k4 = (tid & 7) * 4;
                Bs[k4 + 0][n] = pb.x; Bs[k4 + 1][n] = pb.y;
                Bs[k4 + 2][n] = pb.z; Bs[k4 + 3][n] = pb.w;
            } else {
                int k = tid >> 2, c4 = (tid & 3) * 4;
                Bs[k][c4 + 0] = pb.x; Bs[k][c4 + 1] = pb.y;
                Bs[k][c4 + 2] = pb.z; Bs[k][c4 + 3] = pb.w;
            }
        }
        __syncthreads();

        if (kt + 32 < K) {
            const float* ap0 = (rb > 0) ? A + (ll)am * bStride : A + (ll)am * lda;
            const float* ap1 = (rb > 0) ? A + (ll)(32 + am) * bStride : A + (ll)(32 + am) * lda;
            pa0 = *(const float4*)(ap0 + kt + 32 + ak4);
            pa1 = *(const float4*)(ap1 + kt + 32 + ak4);
            if (tid < 128) {
                if (transb)
                    pb = *(const float4*)(B + (ll)(colBase + (tid >> 3)) * ldb + kt + 32 + (tid & 7) * 4);
                else
                    pb = *(const float4*)(B + (ll)(kt + 32 + (tid >> 2)) * ldb + colBase + (tid & 3) * 4);
            }
        }

#pragma unroll
        for (int kk = 0; kk < 32; kk++) {
            float bv = Bs[kk][c];
            float4 a = *(const float4*)&As[kk][r4 * 4];
            acc[0] += a.x * bv; acc[1] += a.y * bv;
            acc[2] += a.z * bv; acc[3] += a.w * bv;
        }
        __syncthreads();
    }
    const float bb = bias ? bsc * bias[colBase + c] : 0.f;
#pragma unroll
    for (int i = 0; i < 4; i++)
        C[(ll)(r4 * 4 + i) * ldc + colBase + c] = asc * acc[i] + bb;
}

// ================= fused front: stage1(ga|go) -> stage2(ga|go) -> wx ================
__global__ void front_k(const float* __restrict__ img,
                        const float* __restrict__ ga_w, const float* __restrict__ ga_b,
                        const float* __restrict__ go_w, const float* __restrict__ go_b,
                        const float* __restrict__ gru_w_ih, const float* __restrict__ gru_b_ih,
                        const float* __restrict__ ga_pool,
                        float* __restrict__ t1, float* __restrict__ t2,
                        float* __restrict__ u, float* __restrict__ hcat,
                        float* __restrict__ wx)
{
    __shared__ float As[32][68];
    __shared__ float Bs[32][17];
    const ll W2 = (ll)D_ * D_;
    const ll BSTR = (ll)NTOK * D_;
    const int bx = blockIdx.x;

    if (bx < 48)
        skinny_tile(img, ga_w + 2 * W2, ga_b + 2 * D_, 1.f, 1.f, t1, D_, D_, D_, D_,
                    1, BSTR, bx * 16, false, As, Bs);
    else if (bx < 96)
        skinny_tile(img, go_w + 2 * W2, go_b + 2 * D_, 1.f, 1.f, t2, D_, D_, D_, D_,
                    1, BSTR, (bx - 48) * 16, false, As, Bs);
    gridbar(&g_cntf, 144);

    const float s1 = g_scal[1];
    if (bx < 48)
        skinny_tile(t1, ga_w + 3 * W2, ga_b + 3 * D_, 1.f, 1.f, u, D_, D_, D_, D_,
                    0, 0, bx * 16, false, As, Bs);
    else if (bx < 96)
        skinny_tile(t2, go_w + 3 * W2, go_b + 3 * D_, s1, s1, hcat + D_, D_, D_, D_, 2 * D_,
                    0, 0, (bx - 48) * 16, false, As, Bs);
    gridbar(&g_cntf, 288);

    const float ap = ga_pool[0];
    skinny_tile(u, gru_w_ih, gru_b_ih, ap, 1.f, wx, D_, D_, D_, 3 * D_,
                0, 0, bx * 16, true, As, Bs);
}

// ================= TF32 tensor-core GEMM NN (Q projection), reg-prefetched =========
__global__ void tf32gemm_k(const float* __restrict__ A, const float* __restrict__ B,
                           const float* __restrict__ bias, float* __restrict__ C,
                           int M, int N, int K, int ldc)
{
    __shared__ float As[128][36];
    __shared__ float Bs[32][132];
    __shared__ float biasS[16][128];

    const int tid = threadIdx.x;
    const int rowBase = blockIdx.y * 128;
    const int colBase = blockIdx.x * 128;
    const int warpId = tid >> 5;
    const int wm = (warpId >> 2) * 64;
    const int wn = (warpId & 3) * 32;

    for (int i = tid; i < 16 * 128; i += 256)
        biasS[i >> 7][i & 127] = bias[colBase + (i & 127)];
    __syncthreads();

    wmma::fragment<wmma::accumulator, 16, 16, 8, float> acc[4][2];
    {
        wmma::fragment<wmma::accumulator, 16, 16, 8, float> bfrag[2];
#pragma unroll
        for (int j = 0; j < 2; j++)
            wmma::load_matrix_sync(bfrag[j], &biasS[0][wn + j * 16], 128, wmma::mem_row_major);
#pragma unroll
        for (int i = 0; i < 4; i++)
#pragma unroll
            for (int j = 0; j < 2; j++) acc[i][j] = bfrag[j];
    }
    __syncthreads();

    const int ar = tid >> 3, ac4 = (tid & 7) * 4;
    const int br = tid >> 5, bc4 = (tid & 31) * 4;

    float4 pa[4], pb[4];
#pragma unroll
    for (int p = 0; p < 4; p++)
        pa[p] = *(const float4*)(A + (ll)(rowBase + p * 32 + ar) * K + ac4);
#pragma unroll
    for (int p = 0; p < 4; p++)
        pb[p] = *(const float4*)(B + (ll)(p * 8 + br) * N + colBase + bc4);

    for (int kt = 0; kt < K; kt += 32) {
#pragma unroll
        for (int p = 0; p < 4; p++) {
            int row = p * 32 + ar;
            As[row][ac4 + 0] = wmma::__float_to_tf32(pa[p].x);
            As[row][ac4 + 1] = wmma::__float_to_tf32(pa[p].y);
            As[row][ac4 + 2] = wmma::__float_to_tf32(pa[p].z);
            As[row][ac4 + 3] = wmma::__float_to_tf32(pa[p].w);
        }
#pragma unroll
        for (int p = 0; p < 4; p++) {
            int row = p * 8 + br;
            Bs[row][bc4 + 0] = wmma::__float_to_tf32(pb[p].x);
            Bs[row][bc4 + 1] = wmma::__float_to_tf32(pb[p].y);
            Bs[row][bc4 + 2] = wmma::__float_to_tf32(pb[p].z);
            Bs[row][bc4 + 3] = wmma::__float_to_tf32(pb[p].w);
        }
        __syncthreads();

        if (kt + 32 < K) {
#pragma unroll
            for (int p = 0; p < 4; p++)
                pa[p] = *(const float4*)(A + (ll)(rowBase + p * 32 + ar) * K + kt + 32 + ac4);
#pragma unroll
            for (int p = 0; p < 4; p++)
                pb[p] = *(const float4*)(B + (ll)(kt + 32 + p * 8 + br) * N + colBase + bc4);
        }

#pragma unroll
        for (int ks = 0; ks < 32; ks += 8) {
            wmma::fragment<wmma::matrix_a, 16, 16, 8, wmma::precision::tf32, wmma::row_major> af[4];
            wmma::fragment<wmma::matrix_b, 16, 16, 8, wmma::precision::tf32, wmma::row_major> bf[2];
#pragma unroll
            for (int i = 0; i < 4; i++) wmma::load_matrix_sync(af[i], &As[wm + i * 16][ks], 36);
#pragma unroll
            for (int j = 0; j < 2; j++) wmma::load_matrix_sync(bf[j], &Bs[ks][wn + j * 16], 132);
#pragma unroll
            for (int i = 0; i < 4; i++)
#pragma unroll
                for (int j = 0; j < 2; j++) wmma::mma_sync(acc[i][j], af[i], bf[j], acc[i][j]);
        }
        __syncthreads();
    }

#pragma unroll
    for (int i = 0; i < 4; i++)
#pragma unroll
        for (int j = 0; j < 2; j++)
            wmma::store_matrix_sync(&C[(ll)(rowBase + wm + i * 16) * ldc + colBase + wn + j * 16],
                                    acc[i][j], ldc, wmma::mem_row_major);
}

// ========= TF32 NT GEMM, both heads in one launch (blockIdx.z = head), prefetched ====
__global__ void tc_nt2_k(const float* __restrict__ Q, const float* __restrict__ Wk,
                         float* __restrict__ Qt)
{
    __shared__ float smem[2 * 64 * 36];
    float* As = smem;
    float* Bs = smem + 64 * 36;
    const int h = blockIdx.z;
    const float* A = Q + h * DK_;
    const float* B = Wk + h * DK_;
    float* C = Qt + (ll)h * M_Q * D_;
    const int rowBase = blockIdx.y * 64;
    const int colBase = blockIdx.x * 64;
    const int tid = threadIdx.x;
    const int warp = tid >> 5;
    const int wm = (warp >> 2) * 32;
    const int wn = (warp & 3) * 16;

    wmma::fragment<wmma::accumulator, 16, 16, 8, float> acc[2];
    wmma::fill_fragment(acc[0], 0.f);
    wmma::fill_fragment(acc[1], 0.f);

    const int r = tid >> 3, k4 = (tid & 7) * 4;

    float4 pa[2], pb[2];
#pragma unroll
    for (int p = 0; p < 2; p++) {
        pa[p] = *(const float4*)(A + (ll)(rowBase + p * 32 + r) * D_ + k4);
        pb[p] = *(const float4*)(B + (ll)(colBase + p * 32 + r) * D_ + k4);
    }

    for (int kt = 0; kt < DK_; kt += 32) {
#pragma unroll
        for (int p = 0; p < 2; p++) {
            float* d = As + (p * 32 + r) * 36 + k4;
            d[0] = wmma::__float_to_tf32(pa[p].x); d[1] = wmma::__float_to_tf32(pa[p].y);
            d[2] = wmma::__float_to_tf32(pa[p].z); d[3] = wmma::__float_to_tf32(pa[p].w);
            float* e = Bs + (p * 32 + r) * 36 + k4;
            e[0] = wmma::__float_to_tf32(pb[p].x); e[1] = wmma::__float_to_tf32(pb[p].y);
            e[2] = wmma::__float_to_tf32(pb[p].z); e[3] = wmma::__float_to_tf32(pb[p].w);
        }
        __syncthreads();
        if (kt + 32 < DK_) {
#pragma unroll
            for (int p = 0; p < 2; p++) {
                pa[p] = *(const float4*)(A + (ll)(rowBase + p * 32 + r) * D_ + kt + 32 + k4);
                pb[p] = *(const float4*)(B + (ll)(colBase + p * 32 + r) * D_ + kt + 32 + k4);
            }
        }
#pragma unroll
        for (int ks = 0; ks < 32; ks += 8) {
            wmma::fragment<wmma::matrix_a, 16, 16, 8, wmma::precision::tf32, wmma::row_major> af[2];
            wmma::fragment<wmma::matrix_b, 16, 16, 8, wmma::precision::tf32, wmma::col_major> bf;
            wmma::load_matrix_sync(af[0], As + (wm + 0) * 36 + ks, 36);
            wmma::load_matrix_sync(af[1], As + (wm + 16) * 36 + ks, 36);
            wmma::load_matrix_sync(bf, Bs + wn * 36 + ks, 36);
            wmma::mma_sync(acc[0], af[0], bf, acc[0]);
            wmma::mma_sync(acc[1], af[1], bf, acc[1]);
        }
        __syncthreads();
    }
    wmma::store_matrix_sync(&C[(ll)(rowBase + wm + 0) * D_ + colBase + wn], acc[0], D_, wmma::mem_row_major);
    wmma::store_matrix_sync(&C[(ll)(rowBase + wm + 16) * D_ + colBase + wn], acc[1], D_, wmma::mem_row_major);
}

// ================= TF32 scores, reg-prefetched =================
__global__ void scores_tc_k(const float* __restrict__ Qt, const float* __restrict__ img,
                            const float* __restrict__ qb, float* __restrict__ S)
{
    __shared__ float smem[2 * 64 * 36];
    float* As = smem;
    float* Bs = smem + 64 * 36;
    const int b = blockIdx.y;
    const int n0 = blockIdx.x * 64;
    const int tid = threadIdx.x;
    const int warp = tid >> 5;
    const int wm = (warp >> 2) * 32;
    const int wn = (warp & 3) * 16;

    wmma::fragment<wmma::accumulator, 16, 16, 8, float> acc[2];
    wmma::fill_fragment(acc[0], 0.f);
    wmma::fill_fragment(acc[1], 0.f);

    const int r = tid >> 3, k4 = (tid & 7) * 4;
    const float* imgb = img + (ll)b * NTOK * D_ + D_;

    float4 pa[2], pb[2];
#pragma unroll
    for (int p = 0; p < 2; p++) {
        int m = p * 32 + r;
        int h = m >> 5, q = m & 31;
        pa[p] = *(const float4*)(Qt + (ll)h * M_Q * D_ + ((ll)b * T_ + q) * D_ + k4);
        int n = p * 32 + r;
        pb[p] = (n0 + n < NLOC) ? *(const float4*)(imgb + (ll)(n0 + n) * D_ + k4)
                                : make_float4(0.f, 0.f, 0.f, 0.f);
    }

    for (int kt = 0; kt < D_; kt += 32) {
#pragma unroll
        for (int p = 0; p < 2; p++) {
            int m = p * 32 + r;
            float* d = As + m * 36 + k4;
            d[0] = wmma::__float_to_tf32(pa[p].x); d[1] = wmma::__float_to_tf32(pa[p].y);
            d[2] = wmma::__float_to_tf32(pa[p].z); d[3] = wmma::__float_to_tf32(pa[p].w);
            float* e = Bs + m * 36 + k4;
            e[0] = wmma::__float_to_tf32(pb[p].x); e[1] = wmma::__float_to_tf32(pb[p].y);
            e[2] = wmma::__float_to_tf32(pb[p].z); e[3] = wmma::__float_to_tf32(pb[p].w);
        }
        __syncthreads();
        if (kt + 32 < D_) {
#pragma unroll
            for (int p = 0; p < 2; p++) {
                int m = p * 32 + r;
                int h = m >> 5, q = m & 31;
                pa[p] = *(const float4*)(Qt + (ll)h * M_Q * D_ + ((ll)b * T_ + q) * D_ + kt + 32 + k4);
                int n = p * 32 + r;
                pb[p] = (n0 + n < NLOC) ? *(const float4*)(imgb + (ll)(n0 + n) * D_ + kt + 32 + k4)
                                        : make_float4(0.f, 0.f, 0.f, 0.f);
            }
        }
#pragma unroll
        for (int ks = 0; ks < 32; ks += 8) {
            wmma::fragment<wmma::matrix_a, 16, 16, 8, wmma::precision::tf32, wmma::row_major> af[2];
            wmma::fragment<wmma::matrix_b, 16, 16, 8, wmma::precision::tf32, wmma::col_major> bf;
            wmma::load_matrix_sync(af[0], As + (wm + 0) * 36 + ks, 36);
            wmma::load_matrix_sync(af[1], As + (wm + 16) * 36 + ks, 36);
            wmma::load_matrix_sync(bf, Bs + wn * 36 + ks, 36);
            wmma::mma_sync(acc[0], af[0], bf, acc[0]);
            wmma::mma_sync(acc[1], af[1], bf, acc[1]);
        }
        __syncthreads();
    }
    float* Cs = smem;
    wmma::store_matrix_sync(Cs + (wm + 0) * 64 + wn, acc[0], 64, wmma::mem_row_major);
    wmma::store_matrix_sync(Cs + (wm + 16) * 64 + wn, acc[1], 64, wmma::mem_row_major);
    __syncthreads();
    const float scale = rsqrtf((float)DK_);
    for (int idx = tid; idx < 64 * 64; idx += 256) {
        int m = idx >> 6, n = idx & 63;
        if (n0 + n < NLOC) {
            int h = m >> 5, q = m & 31;
            S[((ll)(b * 2 + h) * T_ + q) * NLOC + n0 + n] =
                (Cs[idx] + qb[h * M_Q + b * T_ + q]) * scale;
        }
    }
}

// ================= skinny GEMM launcher kernel (M=64), reg-prefetched =========
template <bool TRANSB, bool RELU>
__global__ void skinny_k(const float* __restrict__ A, const float* __restrict__ B,
                         const float* __restrict__ bias,
                         const float* __restrict__ accScale,
                         const float* __restrict__ biasScale,
                         float* __restrict__ C, int K,
                         int lda, int ldb, int ldc, int rb, ll bStride)
{
    __shared__ float As[32][68];
    __shared__ float Bs[32][17];
    const int tid = threadIdx.x;
    const int colBase = blockIdx.x * 16;
    const int c = tid & 15, r4 = tid >> 4;
    float acc[4] = {0.f, 0.f, 0.f, 0.f};
    const int am = tid >> 3, ak4 = (tid & 7) * 4;

    float4 pa0, pa1, pb;
    {
        const float* ap0 = (rb > 0) ? A + (ll)am * bStride : A + (ll)am * lda;
        const float* ap1 = (rb > 0) ? A + (ll)(32 + am) * bStride : A + (ll)(32 + am) * lda;
        pa0 = *(const float4*)(ap0 + ak4);
        pa1 = *(const float4*)(ap1 + ak4);
        if (tid < 128) {
            if (TRANSB)
                pb = *(const float4*)(B + (ll)(colBase + (tid >> 3)) * ldb + (tid & 7) * 4);
            else
                pb = *(const float4*)(B + (ll)(tid >> 2) * ldb + colBase + (tid & 3) * 4);
        }
    }

    for (int kt = 0; kt < K; kt += 32) {
        As[ak4 + 0][am] = pa0.x; As[ak4 + 1][am] = pa0.y;
        As[ak4 + 2][am] = pa0.z; As[ak4 + 3][am] = pa0.w;
        As[ak4 + 0][32 + am] = pa1.x; As[ak4 + 1][32 + am] = pa1.y;
        As[ak4 + 2][32 + am] = pa1.z; As[ak4 + 3][32 + am] = pa1.w;
        if (tid < 128) {
            if (TRANSB) {
                int n = tid >> 3, k4 = (tid & 7) * 4;
                Bs[k4 + 0][n] = pb.x; Bs[k4 + 1][n] = pb.y;
                Bs[k4 + 2][n] = pb.z; Bs[k4 + 3][n] = pb.w;
            } else {
                int k = tid >> 2, c4 = (tid & 3) * 4;
                Bs[k][c4 + 0] = pb.x; Bs[k][c4 + 1] = pb.y;
                Bs[k][c4 + 2] = pb.z; Bs[k][c4 + 3] = pb.w;
            }
        }
        __syncthreads();

        if (kt + 32 < K) {
            const float* ap0 = (rb > 0) ? A + (ll)am * bStride : A + (ll)am * lda;
            const float* ap1 = (rb > 0) ? A + (ll)(32 + am) * bStride : A + (ll)(32 + am) * lda;
            pa0 = *(const float4*)(ap0 + kt + 32 + ak4);
            pa1 = *(const float4*)(ap1 + kt + 32 + ak4);
            if (tid < 128) {
                if (TRANSB)
                    pb = *(const float4*)(B + (ll)(colBase + (tid >> 3)) * ldb + kt + 32 + (tid & 7) * 4);
                else
                    pb = *(const float4*)(B + (ll)(kt + 32 + (tid >> 2)) * ldb + colBase + (tid & 3) * 4);
            }
        }

#pragma unroll
        for (int kk = 0; kk < 32; kk++) {
            float bv = Bs[kk][c];
            float4 a = *(const float4*)&As[kk][r4 * 4];
            acc[0] += a.x * bv; acc[1] += a.y * bv;
            acc[2] += a.z * bv; acc[3] += a.w * bv;
        }
        __syncthreads();
    }
    const float asc = accScale ? *accScale : 1.f;
    const float bb = bias ? (biasScale ? *biasScale : 1.f) * bias[colBase + c] : 0.f;
#pragma unroll
    for (int i = 0; i < 4; i++) {
        float v = asc * acc[i] + bb;
        if (RELU) v = fmaxf(v, 0.f);
        C[(ll)(r4 * 4 + i) * ldc + colBase + c] = v;
    }
}

// ======= dual-tenant skinny NN GEMM (two problems, one launch), reg-prefetched =======
__global__ void skinny2_k(const float* __restrict__ A1, const float* __restrict__ B1,
                          const float* __restrict__ bias1, const float* __restrict__ asc1,
                          const float* __restrict__ bsc1, float* __restrict__ C1, int ldc1,
                          const float* __restrict__ A2, const float* __restrict__ B2,
                          const float* __restrict__ bias2, const float* __restrict__ asc2,
                          const float* __restrict__ bsc2, float* __restrict__ C2, int ldc2,
                          int n1b, int K, int lda, int ldb, int rb, ll bStride)
{
    __shared__ float As[32][68];
    __shared__ float Bs[32][17];
    const bool sel = blockIdx.x < (unsigned)n1b;
    const float* A = sel ? A1 : A2;
    const float* B = sel ? B1 : B2;
    const float* bias = sel ? bias1 : bias2;
    const float* accScale = sel ? asc1 : asc2;
    const float* biasScale = sel ? bsc1 : bsc2;
    float* C = sel ? C1 : C2;
    const int ldc = sel ? ldc1 : ldc2;
    const int colBase = (sel ? blockIdx.x : blockIdx.x - n1b) * 16;

    float asc = accScale ? *accScale : 1.f;
    float bsc = biasScale ? *biasScale : 1.f;
    skinny_tile(A, B, bias, asc, bsc, C, K, lda, ldb, ldc, rb, bStride, colBase, false, As, Bs);
}

// ---------------- small helpers ----------------
__global__ void pool_sums_k(const float* __restrict__ la_pool, const float* __restrict__ go_pool)
{
    int lane = threadIdx.x;
    float a = la_pool[lane];
    float b = go_pool[lane];
#pragma unroll
    for (int o = 16; o; o >>= 1) {
        a += __shfl_xor_sync(0xffffffffu, a, o);
        b += __shfl_xor_sync(0xffffffffu, b, o);
    }
    if (lane == 0) { g_scal[0] = a; g_scal[1] = b; g_cnt2[0] = 0; g_cnt2[1] = 0; g_cntf = 0; }
}

__global__ void copy_h0_k(const float* __restrict__ h0, float* __restrict__ h)
{
    int i = blockIdx.x * 256 + threadIdx.x;
    h[i] = h0[i];
}

// ======= persistent GRU v2: 96 blocks x 512 threads, BK=64, [b][k] smem, prefetch ====
// Block (j, half): d-slice [16j,16j+16), batches [half*32, +32). Thread (tx,ty):
// d = 16j+tx, b = b0+ty; 3 fp32 accumulators. h tile hs[32][68] loaded as float4 copy.
__global__ void gru_persist_k(const float* __restrict__ wx, const float* __restrict__ Whh,
                              const float* __restrict__ b_hh,
                              float* __restrict__ hA, float* __restrict__ hB,
                              float* __restrict__ qemb)
{
    extern __shared__ float sm[];
    float* ws = sm;                 // [48][772]  weight rows (gate*16+dd) x 768
    float* hs = sm + 48 * 772;      // [32 b][68] h tile, k-contiguous
    const int tid = threadIdx.x;    // 512
    const int j  = blockIdx.x >> 1;
    const int half = blockIdx.x & 1;
    const int b0 = half * 32;
    const int tx = tid & 15;
    const int ty = tid >> 4;        // 0..31 -> one batch per thread

    for (int idx = tid; idx < 48 * 192; idx += 512) {
        int rr = idx / 192, c4 = (idx - rr * 192) * 4;
        int g = rr >> 4, dd = rr & 15;
        float4 v = *(const float4*)(Whh + ((ll)g * D_ + j * 16 + dd) * D_ + c4);
        float* w = ws + rr * 772 + c4;
        w[0] = v.x; w[1] = v.y; w[2] = v.z; w[3] = v.w;
    }
    const int d = j * 16 + tx;
    const int b = b0 + ty;
    float wxr, wxz, wxn;
    {
        ll o = (ll)b * (3 * D_);
        wxr = wx[o + d]; wxz = wx[o + D_ + d]; wxn = wx[o + 2 * D_ + d];
    }
    const float bhr = b_hh[d], bhz = b_hh[D_ + d], bhn = b_hh[2 * D_ + d];
    __syncthreads();

    // staging: thread (hm = tid>>4, hk4 = (tid&15)*4) copies one float4 per tile
    const int hm = tid >> 4;            // 0..31 batch-within-half
    const int hk4 = (tid & 15) * 4;     // 0..60 k-offset

    const float* wr0 = ws + tx * 772;
    const float* wr1 = wr0 + 16 * 772;
    const float* wr2 = wr0 + 32 * 772;
    float* hrow = hs + ty * 68;

    for (int t = 0; t < T_; t++) {
        const float* hin = (t & 1) ? hB : hA;
        float* hout      = (t & 1) ? hA : hB;
        float ar = 0.f, az = 0.f, an = 0.f;

        float4 pv = __ldcg((const float4*)(hin + (ll)(b0 + hm) * D_ + hk4));

        for (int kt = 0; kt < D_; kt += 64) {
            *(float4*)(hs + hm * 68 + hk4) = pv;
            __syncthreads();

            if (kt + 64 < D_)
                pv = __ldcg((const float4*)(hin + (ll)(b0 + hm) * D_ + kt + 64 + hk4));

            const float* w0p = wr0 + kt;
            const float* w1p = wr1 + kt;
            const float* w2p = wr2 + kt;
#pragma unroll
            for (int kk = 0; kk < 64; kk += 4) {
                float4 hh = *(const float4*)(hrow + kk);
                float4 w0 = *(const float4*)(w0p + kk);
                float4 w1 = *(const float4*)(w1p + kk);
                float4 w2 = *(const float4*)(w2p + kk);
                ar += hh.x * w0.x + hh.y * w0.y + hh.z * w0.z + hh.w * w0.w;
                az += hh.x * w1.x + hh.y * w1.y + hh.z * w1.z + hh.w * w1.w;
                an += hh.x * w2.x + hh.y * w2.y + hh.z * w2.z + hh.w * w2.w;
            }
            __syncthreads();
        }

        {
            float hp = __ldcg(hin + (ll)b * D_ + d);
            float r = 1.f / (1.f + __expf(-(wxr + ar + bhr)));
            float z = 1.f / (1.f + __expf(-(wxz + az + bhz)));
            float n = tanhf(wxn + r * (an + bhn));
            float hv = (1.f - z) * n + z * hp;
            __stcg(hout + (ll)b * D_ + d, hv);
            qemb[((ll)b * T_ + t) * D_ + d] = hv;
        }

        if (t < T_ - 1) {
            __syncthreads();
            if (tid == 0) {
                __threadfence();
                atomicAdd(&g_cnt2[half], 1);
                const int target = 48 * (t + 1);
                while (*((volatile int*)&g_cnt2[half]) < target) {}
                __threadfence();
            }
            __syncthreads();
        }
    }
}

// ======= qb[h][m] = Q[m, h*384:+384] . bk[h*384:+384] =======
__global__ void qb_k(const float* __restrict__ Q, const float* __restrict__ bk,
                     float* __restrict__ qb)
{
    int idx = blockIdx.x * 256 + threadIdx.x;
    int h = idx >> 11, m = idx & 2047;
    const float* qr = Q + (ll)m * D_ + h * DK_;
    const float* br = bk + h * DK_;
    float s = 0.f;
#pragma unroll 8
    for (int j = 0; j < DK_; j++) s += qr[j] * br[j];
    qb[idx] = s;
}

// ======= fused softmax + la-pool =======
__global__ void spool_k(const float* __restrict__ S, const float* __restrict__ la,
                        float* __restrict__ wk)
{
    extern __shared__ float sS[];   // [32][901]
    __shared__ float sla[T_];
    const int bh = blockIdx.x;
    const int tid = threadIdx.x;
    if (tid < T_) sla[tid] = la[tid];
    __syncthreads();
    const float* base = S + (ll)bh * T_ * NLOC;
    const int lane = tid & 31, wp = tid >> 5;
    for (int q = wp; q < T_; q += 8) {
        const float* row = base + (ll)q * NLOC;
        float* srow = sS + q * 901;
        float mx = -1e30f;
        for (int k = lane; k < NLOC; k += 32) { float v = row[k]; srow[k] = v; mx = fmaxf(mx, v); }
#pragma unroll
        for (int o = 16; o; o >>= 1) mx = fmaxf(mx, __shfl_xor_sync(0xffffffffu, mx, o));
        float sum = 0.f;
        for (int k = lane; k < NLOC; k += 32) { float e = __expf(srow[k] - mx); srow[k] = e; sum += e; }
#pragma unroll
        for (int o = 16; o; o >>= 1) sum += __shfl_xor_sync(0xffffffffu, sum, o);
        float inv = sla[q] / sum;
        for (int k = lane; k < NLOC; k += 32) srow[k] *= inv;
    }
    __syncthreads();
    for (int k = tid; k < NLOC; k += 256) {
        float s = 0.f;
#pragma unroll
        for (int q = 0; q < T_; q++) s += sS[q * 901 + k];
        wk[(ll)bh * NLOC + k] = s;
    }
}

// ======= pctxi[bh][d] = sum_k wk[bh][k]*img[b,1+k,d]; grid (64 b, 3 d-slices) =======
__global__ void pctxi3_k(const float* __restrict__ wk, const float* __restrict__ img,
                         float* __restrict__ pctxi)
{
    __shared__ float swk[2][NLOC];
    const int b = blockIdx.x;
    const int d = blockIdx.y * 256 + threadIdx.x;
    const int tid = threadIdx.x;
    for (int k = tid; k < 2 * NLOC; k += 256)
        swk[k / NLOC][k % NLOC] = wk[(ll)(b * 2) * NLOC + k];
    __syncthreads();
    const float* ib = img + (ll)b * NTOK * D_ + D_ + d;
    float a0 = 0.f, a1 = 0.f;
#pragma unroll 4
    for (int k = 0; k < NLOC; k++) {
        float v = ib[(ll)k * D_];
        a0 += swk[0][k] * v;
        a1 += swk[1][k] * v;
    }
    pctxi[(ll)(b * 2) * D_ + d] = a0;
    pctxi[(ll)(b * 2 + 1) * D_ + d] = a1;
}

// ---------------- host-side launch wrappers ----------------
static inline void skinny(const float* A, const float* B, const float* bias,
                          const float* asc, const float* bsc, float* C,
                          int N, int K, int lda, int ldb, int ldc,
                          int rb, ll bStride, bool transb, bool relu)
{
    dim3 grid(N / 16);
    if (transb)
        skinny_k<true, false><<<grid, 256>>>(A, B, bias, asc, bsc, C, K, lda, ldb, ldc, rb, bStride);
    else if (relu)
        skinny_k<false, true><<<grid, 256>>>(A, B, bias, asc, bsc, C, K, lda, ldb, ldc, rb, bStride);
    else
        skinny_k<false, false><<<grid, 256>>>(A, B, bias, asc, bsc, C, K, lda, ldb, ldc, rb, bStride);
}

extern "C" void kernel_launch(void* const* d_in, const int* in_sizes, int n_in,
                              void* d_out, int out_size)
{
    (void)in_sizes; (void)n_in; (void)out_size;
    const float* img      = (const float*)d_in[1];
    const float* h0       = (const float*)d_in[2];
    const float* gru_w_ih = (const float*)d_in[3];
    const float* gru_w_hh = (const float*)d_in[4];
    const float* gru_b_ih = (const float*)d_in[5];
    const float* gru_b_hh = (const float*)d_in[6];
    const float* ga_w     = (const float*)d_in[7];
    const float* ga_b     = (const float*)d_in[8];
    const float* ga_pool  = (const float*)d_in[9];
    const float* la_w     = (const float*)d_in[10];
    const float* la_b     = (const float*)d_in[11];
    const float* la_pool  = (const float*)d_in[12];
    const float* go_w     = (const float*)d_in[13];
    const float* go_b     = (const float*)d_in[14];
    const float* go_pool  = (const float*)d_in[15];
    const float* f1_w     = (const float*)d_in[16];
    const float* f1_b     = (const float*)d_in[17];
    const float* f2_w     = (const float*)d_in[18];
    const float* f2_b     = (const float*)d_in[19];
    const float* f3_w     = (const float*)d_in[20];
    const float* f3_b     = (const float*)d_in[21];
    float* out = (float*)d_out;

    float *pt1, *pu, *pt2, *pwx, *ph, *ph2, *pqemb, *pQ, *pQt, *pqb, *pS, *pwk, *ppctxi,
          *ppool, *phcat, *px1, *px2, *pscal;
    cudaGetSymbolAddress((void**)&pt1, g_t1);
    cudaGetSymbolAddress((void**)&pu, g_u);
    cudaGetSymbolAddress((void**)&pt2, g_t2);
    cudaGetSymbolAddress((void**)&pwx, g_wx);
    cudaGetSymbolAddress((void**)&ph, g_h);
    cudaGetSymbolAddress((void**)&ph2, g_h2);
    cudaGetSymbolAddress((void**)&pqemb, g_qemb);
    cudaGetSymbolAddress((void**)&pQ, g_Q);
    cudaGetSymbolAddress((void**)&pQt, g_Qt);
    cudaGetSymbolAddress((void**)&pqb, g_qb);
    cudaGetSymbolAddress((void**)&pS, g_S);
    cudaGetSymbolAddress((void**)&pwk, g_wk);
    cudaGetSymbolAddress((void**)&ppctxi, g_pctxi);
    cudaGetSymbolAddress((void**)&ppool, g_pooled);
    cudaGetSymbolAddress((void**)&phcat, g_hcat);
    cudaGetSymbolAddress((void**)&px1, g_x1);
    cudaGetSymbolAddress((void**)&px2, g_x2);
    cudaGetSymbolAddress((void**)&pscal, g_scal);

    const ll W2 = (ll)D_ * D_;

    const int gru_smem = (48 * 772 + 32 * 68) * 4;       // 156,928
    const int spool_smem = 32 * 901 * 4;                 // 115,328
    cudaFuncSetAttribute(gru_persist_k, cudaFuncAttributeMaxDynamicSharedMemorySize, gru_smem);
    cudaFuncSetAttribute(spool_k, cudaFuncAttributeMaxDynamicSharedMemorySize, spool_smem);

    // app kernel #1: pool sums + counter reset
    pool_sums_k<<<1, 32>>>(la_pool, go_pool);

    // app kernel #2: fused front (stage1 -> stage2 -> wx), persistent 144 blocks
    front_k<<<144, 256>>>(img, ga_w, ga_b, go_w, go_b, gru_w_ih, gru_b_ih, ga_pool,
                          pt1, pt2, pu, phcat, pwx);

    // app kernel #3: h <- h0
    copy_h0_k<<<(BSZ * D_) / 256, 256>>>(h0, ph);

    // app kernel #4 (profiled slot): GRU persistent v2, 32 steps
    gru_persist_k<<<GRU_BLOCKS, 512, gru_smem>>>(pwx, gru_w_hh, gru_b_hh, ph, ph2, pqemb);

    // ---- Q projection (tf32 NN) ----
    {
        dim3 grid(D_ / 128, M_Q / 128);
        tf32gemm_k<<<grid, 256>>>(pqemb, la_w + 0 * W2, la_b + 0 * D_, pQ, M_Q, D_, D_, D_);
    }

    // ---- query-side K projection (tf32 NT, both heads in one launch) ----
    {
        dim3 grid(D_ / 64, M_Q / 64, 2);
        tc_nt2_k<<<grid, 256>>>(pQ, la_w + 1 * W2, pQt);
    }
    qb_k<<<16, 256>>>(pQ, la_b + 1 * D_, pqb);

    // ---- scores (tf32) + fused softmax/pool + pooled ctx ----
    {
        dim3 grid((NLOC + 63) / 64, BSZ);
        scores_tc_k<<<grid, 256>>>(pQt, img, pqb, pS);
    }
    spool_k<<<BSZ * 2, 256, spool_smem>>>(pS, la_pool, pwk);
    {
        dim3 grid(BSZ, 3);
        pctxi3_k<<<grid, 256>>>(pwk, img, ppctxi);
    }

    // ---- pooled V projection (both heads, one launch) ----
    skinny2_k<<<48, 256>>>(ppctxi, la_w + 2 * W2, la_b + 2 * D_, nullptr, pscal, ppool, D_,
                           ppctxi + D_, la_w + 2 * W2 + DK_, la_b + 2 * D_ + DK_, nullptr, pscal, ppool + DK_, D_,
                           24, D_, 2 * D_, D_, 0, 0);
    // ---- output projection: hcat[:, :768] ----
    skinny(ppool, la_w + 3 * W2, la_b + 3 * D_, nullptr, pscal, phcat, D_, D_, D_, D_, 2 * D_, 0, 0, false, false);

    // ---- MLP head ----
    skinny(phcat, f1_w, f1_b, nullptr, nullptr, px1, 1024, 2 * D_, 2 * D_, 1024, 1024, 0, 0, false, false);
    skinny(px1, f2_w, f2_b, nullptr, nullptr, px2, 512, 1024, 1024, 512, 512, 0, 0, false, true);
    skinny(px2, f3_w, f3_b, nullptr, nullptr, out, 1024, 512, 512, 1024, 1024, 0, 0, false, false);
}

// round 17
// speedup vs baseline: 1.2451x; 1.2451x over previous
#include <cuda_runtime.h>
#include <mma.h>
#include <math.h>

using namespace nvcuda;
typedef long long ll;

#define D_    768
#define BSZ   64
#define T_    32
#define NTOK  901
#define NLOC  900
#define DK_   384
#define M_Q   (BSZ * T_)   // 2048
#define GRU_BLOCKS 96

// ---------------- scratch (static device globals; no allocation) ----------------
__device__ float g_t1[BSZ * D_];
__device__ float g_u[BSZ * D_];
__device__ float g_t2[BSZ * D_];
__device__ float g_wx[BSZ * 3 * D_];
__device__ float g_h[BSZ * D_];
__device__ float g_h2[BSZ * D_];
__device__ float g_qemb[M_Q * D_];
__device__ float g_Q[M_Q * D_];
__device__ float g_Qt[2 * M_Q * D_];
__device__ float g_qb[2 * M_Q];
__device__ float g_S[(ll)BSZ * 2 * T_ * NLOC];
__device__ float g_wk[BSZ * 2 * NLOC];
__device__ float g_pctxi[BSZ * 2 * D_];
__device__ float g_pooled[BSZ * D_];
__device__ float g_hcat[BSZ * 2 * D_];
__device__ float g_x1[BSZ * 1024];
__device__ float g_x2[BSZ * 512];
__device__ float g_scal[2];
__device__ int   g_cnt2[2];   // gru per-half barrier counters
__device__ int   g_cntf;      // front kernel barrier counter

// ---------------- device helpers ----------------
__device__ __forceinline__ void gridbar(int* cnt, int target)
{
    __syncthreads();
    if (threadIdx.x == 0) {
        __threadfence();
        atomicAdd(cnt, 1);
        while (*((volatile int*)cnt) < target) {}
        __threadfence();
    }
    __syncthreads();
}

// one 64xK @ KxN -> 64x16 tile; all 256 threads of the block participate.
__device__ void skinny_tile(const float* __restrict__ A, const float* __restrict__ B,
                            const float* __restrict__ bias, float asc, float bsc,
                            float* __restrict__ C, int K, int lda, int ldb, int ldc,
                            int rb, ll bStride, int colBase, bool transb,
                            float (*As)[68], float (*Bs)[17])
{
    const int tid = threadIdx.x;
    const int c = tid & 15, r4 = tid >> 4;
    float acc[4] = {0.f, 0.f, 0.f, 0.f};
    const int am = tid >> 3, ak4 = (tid & 7) * 4;

    float4 pa0, pa1, pb;
    {
        const float* ap0 = (rb > 0) ? A + (ll)am * bStride : A + (ll)am * lda;
        const float* ap1 = (rb > 0) ? A + (ll)(32 + am) * bStride : A + (ll)(32 + am) * lda;
        pa0 = *(const float4*)(ap0 + ak4);
        pa1 = *(const float4*)(ap1 + ak4);
        if (tid < 128) {
            if (transb)
                pb = *(const float4*)(B + (ll)(colBase + (tid >> 3)) * ldb + (tid & 7) * 4);
            else
                pb = *(const float4*)(B + (ll)(tid >> 2) * ldb + colBase + (tid & 3) * 4);
        }
    }

    for (int kt = 0; kt < K; kt += 32) {
        As[ak4 + 0][am] = pa0.x; As[ak4 + 1][am] = pa0.y;
        As[ak4 + 2][am] = pa0.z; As[ak4 + 3][am] = pa0.w;
        As[ak4 + 0][32 + am] = pa1.x; As[ak4 + 1][32 + am] = pa1.y;
        As[ak4 + 2][32 + am] = pa1.z; As[ak4 + 3][32 + am] = pa1.w;
        if (tid < 128) {
            if (transb) {
                int n = tid >> 3, k4 = (tid & 7) * 4;
                Bs[k4 + 0][n] = pb.x; Bs[k4 + 1][n] = pb.y;
                Bs[k4 + 2][n] = pb.z; Bs[k4 + 3][n] = pb.w;
            } else {
                int k = tid >> 2, c4 = (tid & 3) * 4;
                Bs[k][c4 + 0] = pb.x; Bs[k][c4 + 1] = pb.y;
                Bs[k][c4 + 2] = pb.z; Bs[k][c4 + 3] = pb.w;
            }
        }
        __syncthreads();

        if (kt + 32 < K) {
            const float* ap0 = (rb > 0) ? A + (ll)am * bStride : A + (ll)am * lda;
            const float* ap1 = (rb > 0) ? A + (ll)(32 + am) * bStride : A + (ll)(32 + am) * lda;
            pa0 = *(const float4*)(ap0 + kt + 32 + ak4);
            pa1 = *(const float4*)(ap1 + kt + 32 + ak4);
            if (tid < 128) {
                if (transb)
                    pb = *(const float4*)(B + (ll)(colBase + (tid >> 3)) * ldb + kt + 32 + (tid & 7) * 4);
                else
                    pb = *(const float4*)(B + (ll)(kt + 32 + (tid >> 2)) * ldb + colBase + (tid & 3) * 4);
            }
        }

#pragma unroll
        for (int kk = 0; kk < 32; kk++) {
            float bv = Bs[kk][c];
            float4 a = *(const float4*)&As[kk][r4 * 4];
            acc[0] += a.x * bv; acc[1] += a.y * bv;
            acc[2] += a.z * bv; acc[3] += a.w * bv;
        }
        __syncthreads();
    }
    const float bb = bias ? bsc * bias[colBase + c] : 0.f;
#pragma unroll
    for (int i = 0; i < 4; i++)
        C[(ll)(r4 * 4 + i) * ldc + colBase + c] = asc * acc[i] + bb;
}

// ================= fused front: stage1(ga|go) -> stage2(ga|go) -> wx ================
__global__ void front_k(const float* __restrict__ img,
                        const float* __restrict__ ga_w, const float* __restrict__ ga_b,
                        const float* __restrict__ go_w, const float* __restrict__ go_b,
                        const float* __restrict__ gru_w_ih, const float* __restrict__ gru_b_ih,
                        const float* __restrict__ ga_pool,
                        float* __restrict__ t1, float* __restrict__ t2,
                        float* __restrict__ u, float* __restrict__ hcat,
                        float* __restrict__ wx)
{
    __shared__ float As[32][68];
    __shared__ float Bs[32][17];
    const ll W2 = (ll)D_ * D_;
    const ll BSTR = (ll)NTOK * D_;
    const int bx = blockIdx.x;

    if (bx < 48)
        skinny_tile(img, ga_w + 2 * W2, ga_b + 2 * D_, 1.f, 1.f, t1, D_, D_, D_, D_,
                    1, BSTR, bx * 16, false, As, Bs);
    else if (bx < 96)
        skinny_tile(img, go_w + 2 * W2, go_b + 2 * D_, 1.f, 1.f, t2, D_, D_, D_, D_,
                    1, BSTR, (bx - 48) * 16, false, As, Bs);
    gridbar(&g_cntf, 144);

    const float s1 = g_scal[1];
    if (bx < 48)
        skinny_tile(t1, ga_w + 3 * W2, ga_b + 3 * D_, 1.f, 1.f, u, D_, D_, D_, D_,
                    0, 0, bx * 16, false, As, Bs);
    else if (bx < 96)
        skinny_tile(t2, go_w + 3 * W2, go_b + 3 * D_, s1, s1, hcat + D_, D_, D_, D_, 2 * D_,
                    0, 0, (bx - 48) * 16, false, As, Bs);
    gridbar(&g_cntf, 288);

    const float ap = ga_pool[0];
    skinny_tile(u, gru_w_ih, gru_b_ih, ap, 1.f, wx, D_, D_, D_, 3 * D_,
                0, 0, bx * 16, true, As, Bs);
}

// ================= TF32 tensor-core GEMM NN (Q projection), reg-prefetched =========
__global__ void tf32gemm_k(const float* __restrict__ A, const float* __restrict__ B,
                           const float* __restrict__ bias, float* __restrict__ C,
                           int M, int N, int K, int ldc)
{
    __shared__ float As[128][36];
    __shared__ float Bs[32][132];
    __shared__ float biasS[16][128];

    const int tid = threadIdx.x;
    const int rowBase = blockIdx.y * 128;
    const int colBase = blockIdx.x * 128;
    const int warpId = tid >> 5;
    const int wm = (warpId >> 2) * 64;
    const int wn = (warpId & 3) * 32;

    for (int i = tid; i < 16 * 128; i += 256)
        biasS[i >> 7][i & 127] = bias[colBase + (i & 127)];
    __syncthreads();

    wmma::fragment<wmma::accumulator, 16, 16, 8, float> acc[4][2];
    {
        wmma::fragment<wmma::accumulator, 16, 16, 8, float> bfrag[2];
#pragma unroll
        for (int j = 0; j < 2; j++)
            wmma::load_matrix_sync(bfrag[j], &biasS[0][wn + j * 16], 128, wmma::mem_row_major);
#pragma unroll
        for (int i = 0; i < 4; i++)
#pragma unroll
            for (int j = 0; j < 2; j++) acc[i][j] = bfrag[j];
    }
    __syncthreads();

    const int ar = tid >> 3, ac4 = (tid & 7) * 4;
    const int br = tid >> 5, bc4 = (tid & 31) * 4;

    float4 pa[4], pb[4];
#pragma unroll
    for (int p = 0; p < 4; p++)
        pa[p] = *(const float4*)(A + (ll)(rowBase + p * 32 + ar) * K + ac4);
#pragma unroll
    for (int p = 0; p < 4; p++)
        pb[p] = *(const float4*)(B + (ll)(p * 8 + br) * N + colBase + bc4);

    for (int kt = 0; kt < K; kt += 32) {
#pragma unroll
        for (int p = 0; p < 4; p++) {
            int row = p * 32 + ar;
            As[row][ac4 + 0] = wmma::__float_to_tf32(pa[p].x);
            As[row][ac4 + 1] = wmma::__float_to_tf32(pa[p].y);
            As[row][ac4 + 2] = wmma::__float_to_tf32(pa[p].z);
            As[row][ac4 + 3] = wmma::__float_to_tf32(pa[p].w);
        }
#pragma unroll
        for (int p = 0; p < 4; p++) {
            int row = p * 8 + br;
            Bs[row][bc4 + 0] = wmma::__float_to_tf32(pb[p].x);
            Bs[row][bc4 + 1] = wmma::__float_to_tf32(pb[p].y);
            Bs[row][bc4 + 2] = wmma::__float_to_tf32(pb[p].z);
            Bs[row][bc4 + 3] = wmma::__float_to_tf32(pb[p].w);
        }
        __syncthreads();

        if (kt + 32 < K) {
#pragma unroll
            for (int p = 0; p < 4; p++)
                pa[p] = *(const float4*)(A + (ll)(rowBase + p * 32 + ar) * K + kt + 32 + ac4);
#pragma unroll
            for (int p = 0; p < 4; p++)
                pb[p] = *(const float4*)(B + (ll)(kt + 32 + p * 8 + br) * N + colBase + bc4);
        }

#pragma unroll
        for (int ks = 0; ks < 32; ks += 8) {
            wmma::fragment<wmma::matrix_a, 16, 16, 8, wmma::precision::tf32, wmma::row_major> af[4];
            wmma::fragment<wmma::matrix_b, 16, 16, 8, wmma::precision::tf32, wmma::row_major> bf[2];
#pragma unroll
            for (int i = 0; i < 4; i++) wmma::load_matrix_sync(af[i], &As[wm + i * 16][ks], 36);
#pragma unroll
            for (int j = 0; j < 2; j++) wmma::load_matrix_sync(bf[j], &Bs[ks][wn + j * 16], 132);
#pragma unroll
            for (int i = 0; i < 4; i++)
#pragma unroll
                for (int j = 0; j < 2; j++) wmma::mma_sync(acc[i][j], af[i], bf[j], acc[i][j]);
        }
        __syncthreads();
    }

#pragma unroll
    for (int i = 0; i < 4; i++)
#pragma unroll
        for (int j = 0; j < 2; j++)
            wmma::store_matrix_sync(&C[(ll)(rowBase + wm + i * 16) * ldc + colBase + wn + j * 16],
                                    acc[i][j], ldc, wmma::mem_row_major);
}

// ========= TF32 NT GEMM, both heads in one launch (blockIdx.z = head), prefetched ====
__global__ void tc_nt2_k(const float* __restrict__ Q, const float* __restrict__ Wk,
                         float* __restrict__ Qt)
{
    __shared__ float smem[2 * 64 * 36];
    float* As = smem;
    float* Bs = smem + 64 * 36;
    const int h = blockIdx.z;
    const float* A = Q + h * DK_;
    const float* B = Wk + h * DK_;
    float* C = Qt + (ll)h * M_Q * D_;
    const int rowBase = blockIdx.y * 64;
    const int colBase = blockIdx.x * 64;
    const int tid = threadIdx.x;
    const int warp = tid >> 5;
    const int wm = (warp >> 2) * 32;
    const int wn = (warp & 3) * 16;

    wmma::fragment<wmma::accumulator, 16, 16, 8, float> acc[2];
    wmma::fill_fragment(acc[0], 0.f);
    wmma::fill_fragment(acc[1], 0.f);

    const int r = tid >> 3, k4 = (tid & 7) * 4;

    float4 pa[2], pb[2];
#pragma unroll
    for (int p = 0; p < 2; p++) {
        pa[p] = *(const float4*)(A + (ll)(rowBase + p * 32 + r) * D_ + k4);
        pb[p] = *(const float4*)(B + (ll)(colBase + p * 32 + r) * D_ + k4);
    }

    for (int kt = 0; kt < DK_; kt += 32) {
#pragma unroll
        for (int p = 0; p < 2; p++) {
            float* d = As + (p * 32 + r) * 36 + k4;
            d[0] = wmma::__float_to_tf32(pa[p].x); d[1] = wmma::__float_to_tf32(pa[p].y);
            d[2] = wmma::__float_to_tf32(pa[p].z); d[3] = wmma::__float_to_tf32(pa[p].w);
            float* e = Bs + (p * 32 + r) * 36 + k4;
            e[0] = wmma::__float_to_tf32(pb[p].x); e[1] = wmma::__float_to_tf32(pb[p].y);
            e[2] = wmma::__float_to_tf32(pb[p].z); e[3] = wmma::__float_to_tf32(pb[p].w);
        }
        __syncthreads();
        if (kt + 32 < DK_) {
#pragma unroll
            for (int p = 0; p < 2; p++) {
                pa[p] = *(const float4*)(A + (ll)(rowBase + p * 32 + r) * D_ + kt + 32 + k4);
                pb[p] = *(const float4*)(B + (ll)(colBase + p * 32 + r) * D_ + kt + 32 + k4);
            }
        }
#pragma unroll
        for (int ks = 0; ks < 32; ks += 8) {
            wmma::fragment<wmma::matrix_a, 16, 16, 8, wmma::precision::tf32, wmma::row_major> af[2];
            wmma::fragment<wmma::matrix_b, 16, 16, 8, wmma::precision::tf32, wmma::col_major> bf;
            wmma::load_matrix_sync(af[0], As + (wm + 0) * 36 + ks, 36);
            wmma::load_matrix_sync(af[1], As + (wm + 16) * 36 + ks, 36);
            wmma::load_matrix_sync(bf, Bs + wn * 36 + ks, 36);
            wmma::mma_sync(acc[0], af[0], bf, acc[0]);
            wmma::mma_sync(acc[1], af[1], bf, acc[1]);
        }
        __syncthreads();
    }
    wmma::store_matrix_sync(&C[(ll)(rowBase + wm + 0) * D_ + colBase + wn], acc[0], D_, wmma::mem_row_major);
    wmma::store_matrix_sync(&C[(ll)(rowBase + wm + 16) * D_ + colBase + wn], acc[1], D_, wmma::mem_row_major);
}

// ================= TF32 scores, reg-prefetched =================
__global__ void scores_tc_k(const float* __restrict__ Qt, const float* __restrict__ img,
                            const float* __restrict__ qb, float* __restrict__ S)
{
    __shared__ float smem[2 * 64 * 36];
    float* As = smem;
    float* Bs = smem + 64 * 36;
    const int b = blockIdx.y;
    const int n0 = blockIdx.x * 64;
    const int tid = threadIdx.x;
    const int warp = tid >> 5;
    const int wm = (warp >> 2) * 32;
    const int wn = (warp & 3) * 16;

    wmma::fragment<wmma::accumulator, 16, 16, 8, float> acc[2];
    wmma::fill_fragment(acc[0], 0.f);
    wmma::fill_fragment(acc[1], 0.f);

    const int r = tid >> 3, k4 = (tid & 7) * 4;
    const float* imgb = img + (ll)b * NTOK * D_ + D_;

    float4 pa[2], pb[2];
#pragma unroll
    for (int p = 0; p < 2; p++) {
        int m = p * 32 + r;
        int h = m >> 5, q = m & 31;
        pa[p] = *(const float4*)(Qt + (ll)h * M_Q * D_ + ((ll)b * T_ + q) * D_ + k4);
        int n = p * 32 + r;
        pb[p] = (n0 + n < NLOC) ? *(const float4*)(imgb + (ll)(n0 + n) * D_ + k4)
                                : make_float4(0.f, 0.f, 0.f, 0.f);
    }

    for (int kt = 0; kt < D_; kt += 32) {
#pragma unroll
        for (int p = 0; p < 2; p++) {
            int m = p * 32 + r;
            float* d = As + m * 36 + k4;
            d[0] = wmma::__float_to_tf32(pa[p].x); d[1] = wmma::__float_to_tf32(pa[p].y);
            d[2] = wmma::__float_to_tf32(pa[p].z); d[3] = wmma::__float_to_tf32(pa[p].w);
            float* e = Bs + m * 36 + k4;
            e[0] = wmma::__float_to_tf32(pb[p].x); e[1] = wmma::__float_to_tf32(pb[p].y);
            e[2] = wmma::__float_to_tf32(pb[p].z); e[3] = wmma::__float_to_tf32(pb[p].w);
        }
        __syncthreads();
        if (kt + 32 < D_) {
#pragma unroll
            for (int p = 0; p < 2; p++) {
                int m = p * 32 + r;
                int h = m >> 5, q = m & 31;
                pa[p] = *(const float4*)(Qt + (ll)h * M_Q * D_ + ((ll)b * T_ + q) * D_ + kt + 32 + k4);
                int n = p * 32 + r;
                pb[p] = (n0 + n < NLOC) ? *(const float4*)(imgb + (ll)(n0 + n) * D_ + kt + 32 + k4)
                                        : make_float4(0.f, 0.f, 0.f, 0.f);
            }
        }
#pragma unroll
        for (int ks = 0; ks < 32; ks += 8) {
            wmma::fragment<wmma::matrix_a, 16, 16, 8, wmma::precision::tf32, wmma::row_major> af[2];
            wmma::fragment<wmma::matrix_b, 16, 16, 8, wmma::precision::tf32, wmma::col_major> bf;
            wmma::load_matrix_sync(af[0], As + (wm + 0) * 36 + ks, 36);
            wmma::load_matrix_sync(af[1], As + (wm + 16) * 36 + ks, 36);
            wmma::load_matrix_sync(bf, Bs + wn * 36 + ks, 36);
            wmma::mma_sync(acc[0], af[0], bf, acc[0]);
            wmma::mma_sync(acc[1], af[1], bf, acc[1]);
        }
        __syncthreads();
    }
    float* Cs = smem;
    wmma::store_matrix_sync(Cs + (wm + 0) * 64 + wn, acc[0], 64, wmma::mem_row_major);
    wmma::store_matrix_sync(Cs + (wm + 16) * 64 + wn, acc[1], 64, wmma::mem_row_major);
    __syncthreads();
    const float scale = rsqrtf((float)DK_);
    for (int idx = tid; idx < 64 * 64; idx += 256) {
        int m = idx >> 6, n = idx & 63;
        if (n0 + n < NLOC) {
            int h = m >> 5, q = m & 31;
            S[((ll)(b * 2 + h) * T_ + q) * NLOC + n0 + n] =
                (Cs[idx] + qb[h * M_Q + b * T_ + q]) * scale;
        }
    }
}

// ================= skinny GEMM launcher kernel (M=64), reg-prefetched =========
template <bool TRANSB, bool RELU>
__global__ void skinny_k(const float* __restrict__ A, const float* __restrict__ B,
                         const float* __restrict__ bias,
                         const float* __restrict__ accScale,
                         const float* __restrict__ biasScale,
                         float* __restrict__ C, int K,
                         int lda, int ldb, int ldc, int rb, ll bStride)
{
    __shared__ float As[32][68];
    __shared__ float Bs[32][17];
    const int tid = threadIdx.x;
    const int colBase = blockIdx.x * 16;
    const int c = tid & 15, r4 = tid >> 4;
    float acc[4] = {0.f, 0.f, 0.f, 0.f};
    const int am = tid >> 3, ak4 = (tid & 7) * 4;

    float4 pa0, pa1, pb;
    {
        const float* ap0 = (rb > 0) ? A + (ll)am * bStride : A + (ll)am * lda;
        const float* ap1 = (rb > 0) ? A + (ll)(32 + am) * bStride : A + (ll)(32 + am) * lda;
        pa0 = *(const float4*)(ap0 + ak4);
        pa1 = *(const float4*)(ap1 + ak4);
        if (tid < 128) {
            if (TRANSB)
                pb = *(const float4*)(B + (ll)(colBase + (tid >> 3)) * ldb + (tid & 7) * 4);
            else
                pb = *(const float4*)(B + (ll)(tid >> 2) * ldb + colBase + (tid & 3) * 4);
        }
    }

    for (int kt = 0; kt < K; kt += 32) {
        As[ak4 + 0][am] = pa0.x; As[ak4 + 1][am] = pa0.y;
        As[ak4 + 2][am] = pa0.z; As[ak4 + 3][am] = pa0.w;
        As[ak4 + 0][32 + am] = pa1.x; As[ak4 + 1][32 + am] = pa1.y;
        As[ak4 + 2][32 + am] = pa1.z; As[ak4 + 3][32 + am] = pa1.w;
        if (tid < 128) {
            if (TRANSB) {
                int n = tid >> 3, k4 = (tid & 7) * 4;
                Bs[k4 + 0][n] = pb.x; Bs[k4 + 1][n] = pb.y;
                Bs[k4 + 2][n] = pb.z; Bs[k4 + 3][n] = pb.w;
            } else {
                int k = tid >> 2, c4 = (tid & 3) * 4;
                Bs[k][c4 + 0] = pb.x; Bs[k][c4 + 1] = pb.y;
                Bs[k][c4 + 2] = pb.z; Bs[k][c4 + 3] = pb.w;
            }
        }
        __syncthreads();

        if (kt + 32 < K) {
            const float* ap0 = (rb > 0) ? A + (ll)am * bStride : A + (ll)am * lda;
            const float* ap1 = (rb > 0) ? A + (ll)(32 + am) * bStride : A + (ll)(32 + am) * lda;
            pa0 = *(const float4*)(ap0 + kt + 32 + ak4);
            pa1 = *(const float4*)(ap1 + kt + 32 + ak4);
            if (tid < 128) {
                if (TRANSB)
                    pb = *(const float4*)(B + (ll)(colBase + (tid >> 3)) * ldb + kt + 32 + (tid & 7) * 4);
                else
                    pb = *(const float4*)(B + (ll)(kt + 32 + (tid >> 2)) * ldb + colBase + (tid & 3) * 4);
            }
        }

#pragma unroll
        for (int kk = 0; kk < 32; kk++) {
            float bv = Bs[kk][c];
            float4 a = *(const float4*)&As[kk][r4 * 4];
            acc[0] += a.x * bv; acc[1] += a.y * bv;
            acc[2] += a.z * bv; acc[3] += a.w * bv;
        }
        __syncthreads();
    }
    const float asc = accScale ? *accScale : 1.f;
    const float bb = bias ? (biasScale ? *biasScale : 1.f) * bias[colBase + c] : 0.f;
#pragma unroll
    for (int i = 0; i < 4; i++) {
        float v = asc * acc[i] + bb;
        if (RELU) v = fmaxf(v, 0.f);
        C[(ll)(r4 * 4 + i) * ldc + colBase + c] = v;
    }
}

// ======= dual-tenant skinny NN GEMM (two problems, one launch), reg-prefetched =======
__global__ void skinny2_k(const float* __restrict__ A1, const float* __restrict__ B1,
                          const float* __restrict__ bias1, const float* __restrict__ asc1,
                          const float* __restrict__ bsc1, float* __restrict__ C1, int ldc1,
                          const float* __restrict__ A2, const float* __restrict__ B2,
                          const float* __restrict__ bias2, const float* __restrict__ asc2,
                          const float* __restrict__ bsc2, float* __restrict__ C2, int ldc2,
                          int n1b, int K, int lda, int ldb, int rb, ll bStride)
{
    __shared__ float As[32][68];
    __shared__ float Bs[32][17];
    const bool sel = blockIdx.x < (unsigned)n1b;
    const float* A = sel ? A1 : A2;
    const float* B = sel ? B1 : B2;
    const float* bias = sel ? bias1 : bias2;
    const float* accScale = sel ? asc1 : asc2;
    const float* biasScale = sel ? bsc1 : bsc2;
    float* C = sel ? C1 : C2;
    const int ldc = sel ? ldc1 : ldc2;
    const int colBase = (sel ? blockIdx.x : blockIdx.x - n1b) * 16;

    float asc = accScale ? *accScale : 1.f;
    float bsc = biasScale ? *biasScale : 1.f;
    skinny_tile(A, B, bias, asc, bsc, C, K, lda, ldb, ldc, rb, bStride, colBase, false, As, Bs);
}

// ---------------- small helpers ----------------
__global__ void pool_sums_k(const float* __restrict__ la_pool, const float* __restrict__ go_pool)
{
    int lane = threadIdx.x;
    float a = la_pool[lane];
    float b = go_pool[lane];
#pragma unroll
    for (int o = 16; o; o >>= 1) {
        a += __shfl_xor_sync(0xffffffffu, a, o);
        b += __shfl_xor_sync(0xffffffffu, b, o);
    }
    if (lane == 0) { g_scal[0] = a; g_scal[1] = b; g_cnt2[0] = 0; g_cnt2[1] = 0; g_cntf = 0; }
}

__global__ void copy_h0_k(const float* __restrict__ h0, float* __restrict__ h)
{
    int i = blockIdx.x * 256 + threadIdx.x;
    h[i] = h0[i];
}

// ======= persistent GRU v3: R15 structure + h-tile register prefetch + BK=64 =======
// 96 blocks x 256 threads; block (j, half); [k][b] smem layout (conflict-free);
// 2 batches x 3 gates per thread (6 fp32 accumulators).
__global__ void gru_persist_k(const float* __restrict__ wx, const float* __restrict__ Whh,
                              const float* __restrict__ b_hh,
                              float* __restrict__ hA, float* __restrict__ hB,
                              float* __restrict__ qemb)
{
    extern __shared__ float sm[];
    float* ws = sm;                 // [48][772]
    float* hs = sm + 48 * 772;      // [64 k][36 b]
    const int tid = threadIdx.x;    // 256
    const int j  = blockIdx.x >> 1;
    const int half = blockIdx.x & 1;
    const int b0 = half * 32;
    const int tx = tid & 15;
    const int ty = tid >> 4;

    for (int idx = tid; idx < 48 * 192; idx += 256) {
        int rr = idx / 192, c4 = (idx - rr * 192) * 4;
        int g = rr >> 4, dd = rr & 15;
        float4 v = *(const float4*)(Whh + ((ll)g * D_ + j * 16 + dd) * D_ + c4);
        float* w = ws + rr * 772 + c4;
        w[0] = v.x; w[1] = v.y; w[2] = v.z; w[3] = v.w;
    }
    const int d = j * 16 + tx;
    float wxr[2], wxz[2], wxn[2];
#pragma unroll
    for (int i = 0; i < 2; i++) {
        ll o = (ll)(b0 + ty * 2 + i) * (3 * D_);
        wxr[i] = wx[o + d]; wxz[i] = wx[o + D_ + d]; wxn[i] = wx[o + 2 * D_ + d];
    }
    const float bhr = b_hh[d], bhz = b_hh[D_ + d], bhn = b_hh[2 * D_ + d];
    __syncthreads();

    const int hm = tid >> 3;            // 0..31 (batch within half)
    const int hk4 = (tid & 7) * 4;      // 0..28 (k offset, first 32 of tile)

    for (int t = 0; t < T_; t++) {
        const float* hin = (t & 1) ? hB : hA;
        float* hout      = (t & 1) ? hA : hB;
        float ar0 = 0.f, ar1 = 0.f, az0 = 0.f, az1 = 0.f, an0 = 0.f, an1 = 0.f;

        // prefetch first 64-wide tile (two float4 per thread)
        float4 pv0 = __ldcg((const float4*)(hin + (ll)(b0 + hm) * D_ + hk4));
        float4 pv1 = __ldcg((const float4*)(hin + (ll)(b0 + hm) * D_ + 32 + hk4));

        for (int kt = 0; kt < D_; kt += 64) {
            // stage tile: [k][b] scatter
            hs[(hk4 + 0) * 36 + hm] = pv0.x; hs[(hk4 + 1) * 36 + hm] = pv0.y;
            hs[(hk4 + 2) * 36 + hm] = pv0.z; hs[(hk4 + 3) * 36 + hm] = pv0.w;
            hs[(32 + hk4 + 0) * 36 + hm] = pv1.x; hs[(32 + hk4 + 1) * 36 + hm] = pv1.y;
            hs[(32 + hk4 + 2) * 36 + hm] = pv1.z; hs[(32 + hk4 + 3) * 36 + hm] = pv1.w;
            __syncthreads();

            // prefetch next tile while computing this one
            if (kt + 64 < D_) {
                pv0 = __ldcg((const float4*)(hin + (ll)(b0 + hm) * D_ + kt + 64 + hk4));
                pv1 = __ldcg((const float4*)(hin + (ll)(b0 + hm) * D_ + kt + 96 + hk4));
            }

            const float* w0p = ws + tx * 772 + kt;
            const float* w1p = w0p + 16 * 772;
            const float* w2p = w0p + 32 * 772;
            const float* hp = hs + ty * 2;
#pragma unroll
            for (int kk = 0; kk < 64; kk += 4) {
                float4 w0 = *(const float4*)(w0p + kk);
                float4 w1 = *(const float4*)(w1p + kk);
                float4 w2 = *(const float4*)(w2p + kk);
                float2 h0 = *(const float2*)(hp + (kk + 0) * 36);
                float2 h1 = *(const float2*)(hp + (kk + 1) * 36);
                float2 h2 = *(const float2*)(hp + (kk + 2) * 36);
                float2 h3 = *(const float2*)(hp + (kk + 3) * 36);
                ar0 += h0.x * w0.x + h1.x * w0.y + h2.x * w0.z + h3.x * w0.w;
                ar1 += h0.y * w0.x + h1.y * w0.y + h2.y * w0.z + h3.y * w0.w;
                az0 += h0.x * w1.x + h1.x * w1.y + h2.x * w1.z + h3.x * w1.w;
                az1 += h0.y * w1.x + h1.y * w1.y + h2.y * w1.z + h3.y * w1.w;
                an0 += h0.x * w2.x + h1.x * w2.y + h2.x * w2.z + h3.x * w2.w;
                an1 += h0.y * w2.x + h1.y * w2.y + h2.y * w2.z + h3.y * w2.w;
            }
            __syncthreads();
        }
        {
            int b = b0 + ty * 2;
            float hp0 = __ldcg(hin + (ll)b * D_ + d);
            float hp1 = __ldcg(hin + (ll)(b + 1) * D_ + d);
            float r0 = 1.f / (1.f + __expf(-(wxr[0] + ar0 + bhr)));
            float z0 = 1.f / (1.f + __expf(-(wxz[0] + az0 + bhz)));
            float n0 = tanhf(wxn[0] + r0 * (an0 + bhn));
            float h0n = (1.f - z0) * n0 + z0 * hp0;
            float r1 = 1.f / (1.f + __expf(-(wxr[1] + ar1 + bhr)));
            float z1 = 1.f / (1.f + __expf(-(wxz[1] + az1 + bhz)));
            float n1 = tanhf(wxn[1] + r1 * (an1 + bhn));
            float h1n = (1.f - z1) * n1 + z1 * hp1;
            __stcg(hout + (ll)b * D_ + d, h0n);
            __stcg(hout + (ll)(b + 1) * D_ + d, h1n);
            qemb[((ll)b * T_ + t) * D_ + d] = h0n;
            qemb[((ll)(b + 1) * T_ + t) * D_ + d] = h1n;
        }
        if (t < T_ - 1) {
            __syncthreads();
            if (tid == 0) {
                __threadfence();
                atomicAdd(&g_cnt2[half], 1);
                const int target = 48 * (t + 1);
                while (*((volatile int*)&g_cnt2[half]) < target) {}
                __threadfence();
            }
            __syncthreads();
        }
    }
}

// ======= qb[h][m] = Q[m, h*384:+384] . bk[h*384:+384] =======
__global__ void qb_k(const float* __restrict__ Q, const float* __restrict__ bk,
                     float* __restrict__ qb)
{
    int idx = blockIdx.x * 256 + threadIdx.x;
    int h = idx >> 11, m = idx & 2047;
    const float* qr = Q + (ll)m * D_ + h * DK_;
    const float* br = bk + h * DK_;
    float s = 0.f;
#pragma unroll 8
    for (int j = 0; j < DK_; j++) s += qr[j] * br[j];
    qb[idx] = s;
}

// ======= fused softmax + la-pool =======
__global__ void spool_k(const float* __restrict__ S, const float* __restrict__ la,
                        float* __restrict__ wk)
{
    extern __shared__ float sS[];   // [32][901]
    __shared__ float sla[T_];
    const int bh = blockIdx.x;
    const int tid = threadIdx.x;
    if (tid < T_) sla[tid] = la[tid];
    __syncthreads();
    const float* base = S + (ll)bh * T_ * NLOC;
    const int lane = tid & 31, wp = tid >> 5;
    for (int q = wp; q < T_; q += 8) {
        const float* row = base + (ll)q * NLOC;
        float* srow = sS + q * 901;
        float mx = -1e30f;
        for (int k = lane; k < NLOC; k += 32) { float v = row[k]; srow[k] = v; mx = fmaxf(mx, v); }
#pragma unroll
        for (int o = 16; o; o >>= 1) mx = fmaxf(mx, __shfl_xor_sync(0xffffffffu, mx, o));
        float sum = 0.f;
        for (int k = lane; k < NLOC; k += 32) { float e = __expf(srow[k] - mx); srow[k] = e; sum += e; }
#pragma unroll
        for (int o = 16; o; o >>= 1) sum += __shfl_xor_sync(0xffffffffu, sum, o);
        float inv = sla[q] / sum;
        for (int k = lane; k < NLOC; k += 32) srow[k] *= inv;
    }
    __syncthreads();
    for (int k = tid; k < NLOC; k += 256) {
        float s = 0.f;
#pragma unroll
        for (int q = 0; q < T_; q++) s += sS[q * 901 + k];
        wk[(ll)bh * NLOC + k] = s;
    }
}

// ======= pctxi[bh][d] = sum_k wk[bh][k]*img[b,1+k,d]; grid (64 b, 3 d-slices) =======
__global__ void pctxi3_k(const float* __restrict__ wk, const float* __restrict__ img,
                         float* __restrict__ pctxi)
{
    __shared__ float swk[2][NLOC];
    const int b = blockIdx.x;
    const int d = blockIdx.y * 256 + threadIdx.x;
    const int tid = threadIdx.x;
    for (int k = tid; k < 2 * NLOC; k += 256)
        swk[k / NLOC][k % NLOC] = wk[(ll)(b * 2) * NLOC + k];
    __syncthreads();
    const float* ib = img + (ll)b * NTOK * D_ + D_ + d;
    float a0 = 0.f, a1 = 0.f;
#pragma unroll 4
    for (int k = 0; k < NLOC; k++) {
        float v = ib[(ll)k * D_];
        a0 += swk[0][k] * v;
        a1 += swk[1][k] * v;
    }
    pctxi[(ll)(b * 2) * D_ + d] = a0;
    pctxi[(ll)(b * 2 + 1) * D_ + d] = a1;
}

// ---------------- host-side launch wrappers ----------------
static inline void skinny(const float* A, const float* B, const float* bias,
                          const float* asc, const float* bsc, float* C,
                          int N, int K, int lda, int ldb, int ldc,
                          int rb, ll bStride, bool transb, bool relu)
{
    dim3 grid(N / 16);
    if (transb)
        skinny_k<true, false><<<grid, 256>>>(A, B, bias, asc, bsc, C, K, lda, ldb, ldc, rb, bStride);
    else if (relu)
        skinny_k<false, true><<<grid, 256>>>(A, B, bias, asc, bsc, C, K, lda, ldb, ldc, rb, bStride);
    else
        skinny_k<false, false><<<grid, 256>>>(A, B, bias, asc, bsc, C, K, lda, ldb, ldc, rb, bStride);
}

extern "C" void kernel_launch(void* const* d_in, const int* in_sizes, int n_in,
                              void* d_out, int out_size)
{
    (void)in_sizes; (void)n_in; (void)out_size;
    const float* img      = (const float*)d_in[1];
    const float* h0       = (const float*)d_in[2];
    const float* gru_w_ih = (const float*)d_in[3];
    const float* gru_w_hh = (const float*)d_in[4];
    const float* gru_b_ih = (const float*)d_in[5];
    const float* gru_b_hh = (const float*)d_in[6];
    const float* ga_w     = (const float*)d_in[7];
    const float* ga_b     = (const float*)d_in[8];
    const float* ga_pool  = (const float*)d_in[9];
    const float* la_w     = (const float*)d_in[10];
    const float* la_b     = (const float*)d_in[11];
    const float* la_pool  = (const float*)d_in[12];
    const float* go_w     = (const float*)d_in[13];
    const float* go_b     = (const float*)d_in[14];
    const float* go_pool  = (const float*)d_in[15];
    const float* f1_w     = (const float*)d_in[16];
    const float* f1_b     = (const float*)d_in[17];
    const float* f2_w     = (const float*)d_in[18];
    const float* f2_b     = (const float*)d_in[19];
    const float* f3_w     = (const float*)d_in[20];
    const float* f3_b     = (const float*)d_in[21];
    float* out = (float*)d_out;

    float *pt1, *pu, *pt2, *pwx, *ph, *ph2, *pqemb, *pQ, *pQt, *pqb, *pS, *pwk, *ppctxi,
          *ppool, *phcat, *px1, *px2, *pscal;
    cudaGetSymbolAddress((void**)&pt1, g_t1);
    cudaGetSymbolAddress((void**)&pu, g_u);
    cudaGetSymbolAddress((void**)&pt2, g_t2);
    cudaGetSymbolAddress((void**)&pwx, g_wx);
    cudaGetSymbolAddress((void**)&ph, g_h);
    cudaGetSymbolAddress((void**)&ph2, g_h2);
    cudaGetSymbolAddress((void**)&pqemb, g_qemb);
    cudaGetSymbolAddress((void**)&pQ, g_Q);
    cudaGetSymbolAddress((void**)&pQt, g_Qt);
    cudaGetSymbolAddress((void**)&pqb, g_qb);
    cudaGetSymbolAddress((void**)&pS, g_S);
    cudaGetSymbolAddress((void**)&pwk, g_wk);
    cudaGetSymbolAddress((void**)&ppctxi, g_pctxi);
    cudaGetSymbolAddress((void**)&ppool, g_pooled);
    cudaGetSymbolAddress((void**)&phcat, g_hcat);
    cudaGetSymbolAddress((void**)&px1, g_x1);
    cudaGetSymbolAddress((void**)&px2, g_x2);
    cudaGetSymbolAddress((void**)&pscal, g_scal);

    const ll W2 = (ll)D_ * D_;

    const int gru_smem = (48 * 772 + 64 * 36) * 4;       // 157,440
    const int spool_smem = 32 * 901 * 4;                 // 115,328
    cudaFuncSetAttribute(gru_persist_k, cudaFuncAttributeMaxDynamicSharedMemorySize, gru_smem);
    cudaFuncSetAttribute(spool_k, cudaFuncAttributeMaxDynamicSharedMemorySize, spool_smem);

    // app kernel #1: pool sums + counter reset
    pool_sums_k<<<1, 32>>>(la_pool, go_pool);

    // app kernel #2: fused front (stage1 -> stage2 -> wx), persistent 144 blocks
    front_k<<<144, 256>>>(img, ga_w, ga_b, go_w, go_b, gru_w_ih, gru_b_ih, ga_pool,
                          pt1, pt2, pu, phcat, pwx);

    // app kernel #3: h <- h0
    copy_h0_k<<<(BSZ * D_) / 256, 256>>>(h0, ph);

    // app kernel #4 (profiled slot): GRU persistent v3, 32 steps
    gru_persist_k<<<GRU_BLOCKS, 256, gru_smem>>>(pwx, gru_w_hh, gru_b_hh, ph, ph2, pqemb);

    // ---- Q projection (tf32 NN) ----
    {
        dim3 grid(D_ / 128, M_Q / 128);
        tf32gemm_k<<<grid, 256>>>(pqemb, la_w + 0 * W2, la_b + 0 * D_, pQ, M_Q, D_, D_, D_);
    }

    // ---- query-side K projection (tf32 NT, both heads in one launch) ----
    {
        dim3 grid(D_ / 64, M_Q / 64, 2);
        tc_nt2_k<<<grid, 256>>>(pQ, la_w + 1 * W2, pQt);
    }
    qb_k<<<16, 256>>>(pQ, la_b + 1 * D_, pqb);

    // ---- scores (tf32) + fused softmax/pool + pooled ctx ----
    {
        dim3 grid((NLOC + 63) / 64, BSZ);
        scores_tc_k<<<grid, 256>>>(pQt, img, pqb, pS);
    }
    spool_k<<<BSZ * 2, 256, spool_smem>>>(pS, la_pool, pwk);
    {
        dim3 grid(BSZ, 3);
        pctxi3_k<<<grid, 256>>>(pwk, img, ppctxi);
    }

    // ---- pooled V projection (both heads, one launch) ----
    skinny2_k<<<48, 256>>>(ppctxi, la_w + 2 * W2, la_b + 2 * D_, nullptr, pscal, ppool, D_,
                           ppctxi + D_, la_w + 2 * W2 + DK_, la_b + 2 * D_ + DK_, nullptr, pscal, ppool + DK_, D_,
                           24, D_, 2 * D_, D_, 0, 0);
    // ---- output projection: hcat[:, :768] ----
    skinny(ppool, la_w + 3 * W2, la_b + 3 * D_, nullptr, pscal, phcat, D_, D_, D_, D_, 2 * D_, 0, 0, false, false);

    // ---- MLP head ----
    skinny(phcat, f1_w, f1_b, nullptr, nullptr, px1, 1024, 2 * D_, 2 * D_, 1024, 1024, 0, 0, false, false);
    skinny(px1, f2_w, f2_b, nullptr, nullptr, px2, 512, 1024, 1024, 512, 512, 0, 0, false, true);
    skinny(px2, f3_w, f3_b, nullptr, nullptr, out, 1024, 512, 512, 1024, 1024, 0, 0, false, false);
}